// round 7
// baseline (speedup 1.0000x reference)
#include <cuda_runtime.h>
#include <cuda_bf16.h>
#include <cstdint>

// Problem constants (fixed by setup_inputs)
#define BS    16
#define NQ    900
#define NC    151
#define NT    100
#define TT    (BS * NT)      // 1600 total targets
#define NROWS (BS * NQ)      // 14400 query rows
#define NG    (TT / 4)       // 400 groups of 4 targets

#define THREADS 256
#define ROWS_PER_BLOCK 8
#define PT_PITCH4 3          // prob table: 3 float4 slots per class

// ---- shared layout (static offsets, bytes) ----
#define SM_CX    0           // float[1600]  6400
#define SM_CY    6400
#define SM_WX    12800       // w/2
#define SM_WY    19200       // h/2
#define SM_AR    25600       // w*h
#define SM_PB    32000       // float4[8]      128
#define SM_PT    32128       // float[151*12] 7296 (padded)
#define SM_ID    39424       // int[1600]     6400
#define SM_STAGE 45824       // raw boxes staging 25600
#define SM_MBAR  71424       // 8B mbarrier
#define SMEM_BYTES 71440

__device__ __forceinline__ uint32_t smem_u32(const void* p) {
    return (uint32_t)__cvta_generic_to_shared(p);
}

// cost = 5*L1(cxcywh) + (2 - p) - 2*(inter*earea + uni^2)/(uni*earea)
__device__ __forceinline__ float cost_elem(
    float tcx, float tcy, float twx, float twy, float tarea,
    float base,
    float pcx, float pcy, float pwx, float pwy, float parea)
{
    float adcx = fabsf(pcx - tcx), adcy = fabsf(pcy - tcy);
    float adwx = fabsf(pwx - twx), adwy = fabsf(pwy - twy);
    float sx   = pwx + twx,        sy   = pwy + twy;

    float acc = fmaf(5.0f,  adcx, base);
    acc = fmaf(5.0f,  adcy, acc);
    acc = fmaf(10.0f, adwx, acc);
    acc = fmaf(10.0f, adwy, acc);

    float mx = fmaxf(adcx, adwx), my = fmaxf(adcy, adwy);
    float iw = fmaxf(sx - mx, 0.0f), ih = fmaxf(sy - my, 0.0f);
    float ew = sx + mx,              eh = sy + my;

    float inter = iw * ih;
    float earea = ew * eh;
    float uni   = (parea + tarea) - inter;

    float num = fmaf(uni, uni, inter * earea);
    float q   = __fdividef(num, uni * earea);
    return fmaf(-2.0f, q, acc);
}

extern __shared__ __align__(16) char smem_raw[];

__global__ __launch_bounds__(THREADS, 3)
void matcher_kernel(const float* __restrict__ pred_logits,   // [NROWS, NC]
                    const float* __restrict__ pred_boxes,    // [NROWS, 4]
                    const int*   __restrict__ tgt_labels,    // [TT]
                    const float* __restrict__ tgt_boxes,     // [TT, 4]
                    float*       __restrict__ out)           // [NROWS, TT]
{
    float* s_cx = reinterpret_cast<float*>(smem_raw + SM_CX);
    float* s_cy = reinterpret_cast<float*>(smem_raw + SM_CY);
    float* s_wx = reinterpret_cast<float*>(smem_raw + SM_WX);
    float* s_wy = reinterpret_cast<float*>(smem_raw + SM_WY);
    float* s_ar = reinterpret_cast<float*>(smem_raw + SM_AR);
    float4* s_pb = reinterpret_cast<float4*>(smem_raw + SM_PB);
    float*  s_pT = reinterpret_cast<float*>(smem_raw + SM_PT);
    const int4* s_id4 = reinterpret_cast<const int4*>(smem_raw + SM_ID);
    const float4* stage4 = reinterpret_cast<const float4*>(smem_raw + SM_STAGE);
    const uint32_t mbar = smem_u32(smem_raw + SM_MBAR);

    const int tid  = threadIdx.x;
    const int lane = tid & 31;
    const int warp = tid >> 5;
    const int row_base = blockIdx.x * ROWS_PER_BLOCK;

    // ---- tid0: bulk copies of raw boxes + ids (overlap with softmax) ----
    if (tid == 0) {
        asm volatile("mbarrier.init.shared::cta.b64 [%0], 1;" :: "r"(mbar) : "memory");
        asm volatile("fence.proxy.async.shared::cta;" ::: "memory");
        asm volatile("mbarrier.arrive.expect_tx.shared::cta.b64 _, [%0], %1;"
                     :: "r"(mbar), "r"(25600u + 6400u) : "memory");
        asm volatile("cp.async.bulk.shared::cta.global.mbarrier::complete_tx::bytes "
                     "[%0], [%1], %2, [%3];"
                     :: "r"(smem_u32(smem_raw + SM_STAGE)), "l"((const void*)tgt_boxes),
                        "r"(25600u), "r"(mbar) : "memory");
        asm volatile("cp.async.bulk.shared::cta.global.mbarrier::complete_tx::bytes "
                     "[%0], [%1], %2, [%3];"
                     :: "r"(smem_u32(smem_raw + SM_ID)), "l"((const void*)tgt_labels),
                        "r"(6400u), "r"(mbar) : "memory");
    }
    if (tid < ROWS_PER_BLOCK)
        s_pb[tid] = reinterpret_cast<const float4*>(pred_boxes)[row_base + tid];

    // ---- warp-per-row softmax; store (2 - p) transposed, pitch 12 floats ----
    {
        const float* lg = pred_logits + (row_base + warp) * NC;
        float e[5];
        float s = 0.0f;
        #pragma unroll
        for (int k = 0; k < 5; k++) {
            int c = lane + 32 * k;
            e[k] = (c < NC) ? __expf(lg[c]) : 0.0f;
            s += e[k];
        }
        #pragma unroll
        for (int o = 16; o; o >>= 1)
            s += __shfl_xor_sync(0xffffffffu, s, o);
        const float inv = __fdividef(1.0f, s);
        const int grp = warp >> 2, r = warp & 3;
        #pragma unroll
        for (int k = 0; k < 5; k++) {
            int c = lane + 32 * k;
            if (c < NC) s_pT[(c * PT_PITCH4 + grp) * 4 + r] = fmaf(-e[k], inv, 2.0f);
        }
    }
    __syncthreads();   // orders mbarrier init (tid0) before waits; probs visible later

    // ---- wait for bulk copies, then in-block transform raw -> SoA ----
    {
        uint32_t done = 0;
        while (!done) {
            asm volatile(
                "{.reg .pred p;\n\t"
                "mbarrier.try_wait.parity.acquire.cta.shared::cta.b64 p, [%1], 0, 0x989680;\n\t"
                "selp.b32 %0, 1, 0, p;}"
                : "=r"(done) : "r"(mbar) : "memory");
        }
    }
    for (int i = tid; i < TT; i += THREADS) {
        float4 t = stage4[i];              // cxcywh
        s_cx[i] = t.x;
        s_cy[i] = t.y;
        s_wx[i] = 0.5f * t.z;
        s_wy[i] = 0.5f * t.w;
        s_ar[i] = t.z * t.w;
    }
    __syncthreads();   // SoA + prob table ready

    const float4* probT4 = reinterpret_cast<const float4*>(s_pT);
    const float4* cx4 = reinterpret_cast<const float4*>(s_cx);
    const float4* cy4 = reinterpret_cast<const float4*>(s_cy);
    const float4* wx4 = reinterpret_cast<const float4*>(s_wx);
    const float4* wy4 = reinterpret_cast<const float4*>(s_wy);
    const float4* ar4 = reinterpret_cast<const float4*>(s_ar);

    // ---- output: 2 groups of 4 rows; 4 targets x 4 rows per iteration ----
    #pragma unroll 1
    for (int grp = 0; grp < 2; grp++) {
        const int r0 = row_base + 4 * grp;

        float pcx[4], pcy[4], pwx[4], pwy[4], pa[4];
        #pragma unroll
        for (int r = 0; r < 4; r++) {
            float4 pb = s_pb[4 * grp + r];
            pcx[r] = pb.x;  pcy[r] = pb.y;
            pwx[r] = 0.5f * pb.z; pwy[r] = 0.5f * pb.w;
            pa[r]  = pb.z * pb.w;
        }

        float4* o0 = reinterpret_cast<float4*>(out + (size_t)(r0 + 0) * TT);
        float4* o1 = reinterpret_cast<float4*>(out + (size_t)(r0 + 1) * TT);
        float4* o2 = reinterpret_cast<float4*>(out + (size_t)(r0 + 2) * TT);
        float4* o3 = reinterpret_cast<float4*>(out + (size_t)(r0 + 3) * TT);

        #pragma unroll 1
        for (int g = tid; g < NG; g += THREADS) {
            float4 tcx = cx4[g], tcy = cy4[g];
            float4 twx = wx4[g], twy = wy4[g];
            float4 ta  = ar4[g];
            int4 ids = s_id4[g];

            float4 P0 = probT4[ids.x * PT_PITCH4 + grp];
            float4 P1 = probT4[ids.y * PT_PITCH4 + grp];
            float4 P2 = probT4[ids.z * PT_PITCH4 + grp];
            float4 P3 = probT4[ids.w * PT_PITCH4 + grp];
            const float* p0 = reinterpret_cast<const float*>(&P0);
            const float* p1 = reinterpret_cast<const float*>(&P1);
            const float* p2 = reinterpret_cast<const float*>(&P2);
            const float* p3 = reinterpret_cast<const float*>(&P3);

            float4 v0, v1, v2, v3;
            #pragma unroll
            for (int r = 0; r < 4; r++) {
                float4 v;
                v.x = cost_elem(tcx.x, tcy.x, twx.x, twy.x, ta.x, p0[r],
                                pcx[r], pcy[r], pwx[r], pwy[r], pa[r]);
                v.y = cost_elem(tcx.y, tcy.y, twx.y, twy.y, ta.y, p1[r],
                                pcx[r], pcy[r], pwx[r], pwy[r], pa[r]);
                v.z = cost_elem(tcx.z, tcy.z, twx.z, twy.z, ta.z, p2[r],
                                pcx[r], pcy[r], pwx[r], pwy[r], pa[r]);
                v.w = cost_elem(tcx.w, tcy.w, twx.w, twy.w, ta.w, p3[r],
                                pcx[r], pcy[r], pwx[r], pwy[r], pa[r]);
                if (r == 0) v0 = v; else if (r == 1) v1 = v;
                else if (r == 2) v2 = v; else v3 = v;
            }
            o0[g] = v0;
            o1[g] = v1;
            o2[g] = v2;
            o3[g] = v3;
        }
    }
}

extern "C" void kernel_launch(void* const* d_in, const int* in_sizes, int n_in,
                              void* d_out, int out_size)
{
    const float* pred_logits = (const float*)d_in[0];
    const float* pred_boxes  = (const float*)d_in[1];
    const int*   tgt_labels  = (const int*)  d_in[2];
    const float* tgt_boxes   = (const float*)d_in[3];
    float* out = (float*)d_out;

    cudaFuncSetAttribute(matcher_kernel,
                         cudaFuncAttributeMaxDynamicSharedMemorySize, SMEM_BYTES);
    const int blocks = NROWS / ROWS_PER_BLOCK;   // 1800
    matcher_kernel<<<blocks, THREADS, SMEM_BYTES>>>(
        pred_logits, pred_boxes, tgt_labels, tgt_boxes, out);
}

// round 9
// speedup vs baseline: 1.0277x; 1.0277x over previous
#include <cuda_runtime.h>
#include <cuda_bf16.h>
#include <cstdint>

// Problem constants (fixed by setup_inputs)
#define BS    16
#define NQ    900
#define NC    151
#define NT    100
#define TT    (BS * NT)      // 1600 total targets
#define NROWS (BS * NQ)      // 14400 query rows
#define NG    (TT / 4)       // 400 target records

#define THREADS 256
#define ROWS_PER_BLOCK 8
#define PT_PITCH4 3          // prob table: 3 float4 slots per class

typedef unsigned long long u64;

// ---- packed f32x2 helpers (sm_100+: add/sub/mul/fma only) ----
__device__ __forceinline__ u64 pk2(float lo, float hi) {
    u64 r; asm("mov.b64 %0, {%1, %2};" : "=l"(r) : "f"(lo), "f"(hi)); return r;
}
__device__ __forceinline__ u64 dup2(float x) { return pk2(x, x); }
__device__ __forceinline__ void upk2(float& lo, float& hi, u64 p) {
    asm("mov.b64 {%0, %1}, %2;" : "=f"(lo), "=f"(hi) : "l"(p));
}
__device__ __forceinline__ u64 add2(u64 a, u64 b) {
    u64 r; asm("add.rn.f32x2 %0, %1, %2;" : "=l"(r) : "l"(a), "l"(b)); return r;
}
__device__ __forceinline__ u64 sub2(u64 a, u64 b) {
    u64 r; asm("sub.rn.f32x2 %0, %1, %2;" : "=l"(r) : "l"(a), "l"(b)); return r;
}
__device__ __forceinline__ u64 mul2(u64 a, u64 b) {
    u64 r; asm("mul.rn.f32x2 %0, %1, %2;" : "=l"(r) : "l"(a), "l"(b)); return r;
}
__device__ __forceinline__ u64 fma2(u64 a, u64 b, u64 c) {
    u64 r; asm("fma.rn.f32x2 %0, %1, %2, %3;" : "=l"(r) : "l"(a), "l"(b), "l"(c)); return r;
}
// no max.f32x2 on sm_103a: emulate with scalar FMNMX (alu pipe)
__device__ __forceinline__ u64 max2(u64 a, u64 b) {
    float a0, a1, b0, b1;
    upk2(a0, a1, a); upk2(b0, b1, b);
    return pk2(fmaxf(a0, b0), fmaxf(a1, b1));
}
__device__ __forceinline__ u64 relu2(u64 a) {
    float a0, a1;
    upk2(a0, a1, a);
    return pk2(fmaxf(a0, 0.0f), fmaxf(a1, 0.0f));
}
#define ABS2(x) ((x) & 0x7FFFFFFF7FFFFFFFull)

// 80-byte target record: 4 targets (cx,cy,w/2,h/2) + their 4 areas
struct __align__(16) Rec { float4 v[5]; };
__device__ Rec g_rec[NG];    // prep-kernel output (32000 B)

// ---- shared layout (static offsets, bytes) ----
#define SM_REC   0                       // Rec[400]            32000
#define SM_PB    32000                   // float4[8]             128
#define SM_PT    32128                   // float[151*12 pad]    7296
#define SM_ID    39424                   // int[1600]            6400
#define SM_MBAR  45824                   // 8B mbarrier
#define SMEM_BYTES 45840

__device__ __forceinline__ uint32_t smem_u32(const void* p) {
    return (uint32_t)__cvta_generic_to_shared(p);
}

// ---- prep: transform targets into 80B records (runs once per replay) ----
__global__ void prep_kernel(const float* __restrict__ tgt_boxes)
{
    int i = blockIdx.x * blockDim.x + threadIdx.x;
    if (i >= TT) return;
    float4 t = reinterpret_cast<const float4*>(tgt_boxes)[i];
    g_rec[i >> 2].v[i & 3] = make_float4(t.x, t.y, 0.5f * t.z, 0.5f * t.w);
    reinterpret_cast<float*>(&g_rec[i >> 2].v[4])[i & 3] = t.z * t.w;
}

extern __shared__ __align__(16) char smem_raw[];

__global__ __launch_bounds__(THREADS, 3)
void matcher_kernel(const float* __restrict__ pred_logits,   // [NROWS, NC]
                    const float* __restrict__ pred_boxes,    // [NROWS, 4]
                    const int*   __restrict__ tgt_labels,    // [TT]
                    float*       __restrict__ out)           // [NROWS, TT]
{
    const Rec*  s_rec = reinterpret_cast<const Rec*>(smem_raw + SM_REC);
    float4*     s_pb  = reinterpret_cast<float4*>(smem_raw + SM_PB);
    float*      s_pT  = reinterpret_cast<float*>(smem_raw + SM_PT);
    const int4* s_id4 = reinterpret_cast<const int4*>(smem_raw + SM_ID);
    const uint32_t mbar = smem_u32(smem_raw + SM_MBAR);

    const int tid  = threadIdx.x;
    const int lane = tid & 31;
    const int warp = tid >> 5;
    const int row_base = blockIdx.x * ROWS_PER_BLOCK;

    // ---- tid0: kick off bulk copies of records + ids (overlaps softmax) ----
    if (tid == 0) {
        asm volatile("mbarrier.init.shared::cta.b64 [%0], 1;" :: "r"(mbar) : "memory");
        asm volatile("fence.proxy.async.shared::cta;" ::: "memory");
        asm volatile("mbarrier.arrive.expect_tx.shared::cta.b64 _, [%0], %1;"
                     :: "r"(mbar), "r"(32000u + 6400u) : "memory");
        asm volatile("cp.async.bulk.shared::cta.global.mbarrier::complete_tx::bytes "
                     "[%0], [%1], %2, [%3];"
                     :: "r"(smem_u32(smem_raw + SM_REC)), "l"((const void*)g_rec),
                        "r"(32000u), "r"(mbar) : "memory");
        asm volatile("cp.async.bulk.shared::cta.global.mbarrier::complete_tx::bytes "
                     "[%0], [%1], %2, [%3];"
                     :: "r"(smem_u32(smem_raw + SM_ID)), "l"((const void*)tgt_labels),
                        "r"(6400u), "r"(mbar) : "memory");
    }
    if (tid < ROWS_PER_BLOCK)
        s_pb[tid] = reinterpret_cast<const float4*>(pred_boxes)[row_base + tid];

    // ---- warp-per-row softmax; store (2 - p) transposed, pitch 12 floats ----
    {
        const float* lg = pred_logits + (row_base + warp) * NC;
        float e[5];
        float s = 0.0f;
        #pragma unroll
        for (int k = 0; k < 5; k++) {
            int c = lane + 32 * k;
            e[k] = (c < NC) ? __expf(lg[c]) : 0.0f;
            s += e[k];
        }
        #pragma unroll
        for (int o = 16; o; o >>= 1)
            s += __shfl_xor_sync(0xffffffffu, s, o);
        const float inv = __fdividef(1.0f, s);
        const int grp = warp >> 2, r = warp & 3;
        #pragma unroll
        for (int k = 0; k < 5; k++) {
            int c = lane + 32 * k;
            if (c < NC) s_pT[(c * PT_PITCH4 + grp) * 4 + r] = fmaf(-e[k], inv, 2.0f);
        }
    }
    __syncthreads();

    // ---- wait for bulk copies ----
    {
        uint32_t done = 0;
        while (!done) {
            asm volatile(
                "{.reg .pred p;\n\t"
                "mbarrier.try_wait.parity.acquire.cta.shared::cta.b64 p, [%1], 0, 0x989680;\n\t"
                "selp.b32 %0, 1, 0, p;}"
                : "=r"(done) : "r"(mbar) : "memory");
        }
    }

    const ulonglong2* probT2 = reinterpret_cast<const ulonglong2*>(s_pT);
    const u64 C5  = dup2(5.0f);
    const u64 C10 = dup2(10.0f);

    // ---- output: 2 groups of 4 rows; 4 targets x 4 rows per iteration ----
    #pragma unroll 1
    for (int grp = 0; grp < 2; grp++) {
        const int r0 = row_base + 4 * grp;

        // packed row-pair constants: q=0 -> rows (0,1), q=1 -> rows (2,3)
        u64 pcx2[2], pcy2[2], pwx2[2], pwy2[2], pa2[2];
        #pragma unroll
        for (int q = 0; q < 2; q++) {
            float4 pbA = s_pb[4 * grp + 2 * q];
            float4 pbB = s_pb[4 * grp + 2 * q + 1];
            pcx2[q] = pk2(pbA.x, pbB.x);
            pcy2[q] = pk2(pbA.y, pbB.y);
            pwx2[q] = pk2(0.5f * pbA.z, 0.5f * pbB.z);
            pwy2[q] = pk2(0.5f * pbA.w, 0.5f * pbB.w);
            pa2[q]  = pk2(pbA.z * pbA.w, pbB.z * pbB.w);
        }

        float4* o0 = reinterpret_cast<float4*>(out + (size_t)(r0 + 0) * TT);
        float4* o1 = reinterpret_cast<float4*>(out + (size_t)(r0 + 1) * TT);
        float4* o2 = reinterpret_cast<float4*>(out + (size_t)(r0 + 2) * TT);
        float4* o3 = reinterpret_cast<float4*>(out + (size_t)(r0 + 3) * TT);

        #pragma unroll 1
        for (int g = tid; g < NG; g += THREADS) {
            const Rec& rc = s_rec[g];
            float4 ta = rc.v[4];
            int4 ids = s_id4[g];

            // (2-p) pairs straight from LDS.128 as u64s
            ulonglong2 PR[4];
            PR[0] = probT2[ids.x * PT_PITCH4 + grp];
            PR[1] = probT2[ids.y * PT_PITCH4 + grp];
            PR[2] = probT2[ids.z * PT_PITCH4 + grp];
            PR[3] = probT2[ids.w * PT_PITCH4 + grp];

            float res[4][4];   // [row][target]

            #pragma unroll
            for (int t = 0; t < 4; t++) {
                float4 T = rc.v[t];
                const float tar = (t == 0) ? ta.x : (t == 1) ? ta.y
                                 : (t == 2) ? ta.z : ta.w;
                u64 tcx = dup2(T.x), tcy = dup2(T.y);
                u64 twx = dup2(T.z), twy = dup2(T.w);
                u64 ta2 = dup2(tar);

                #pragma unroll
                for (int q = 0; q < 2; q++) {
                    u64 adcx = ABS2(sub2(pcx2[q], tcx));
                    u64 adcy = ABS2(sub2(pcy2[q], tcy));
                    u64 adwx = ABS2(sub2(pwx2[q], twx));
                    u64 adwy = ABS2(sub2(pwy2[q], twy));
                    u64 sx = add2(pwx2[q], twx);
                    u64 sy = add2(pwy2[q], twy);

                    u64 base = (q == 0) ? PR[t].x : PR[t].y;
                    u64 acc = fma2(C5,  adcx, base);
                    acc = fma2(C5,  adcy, acc);
                    acc = fma2(C10, adwx, acc);
                    acc = fma2(C10, adwy, acc);

                    u64 mx = max2(adcx, adwx);
                    u64 my = max2(adcy, adwy);
                    u64 iw = relu2(sub2(sx, mx));
                    u64 ih = relu2(sub2(sy, my));
                    u64 ew = add2(sx, mx);
                    u64 eh = add2(sy, my);

                    u64 inter = mul2(iw, ih);
                    u64 earea = mul2(ew, eh);
                    u64 uni   = sub2(add2(pa2[q], ta2), inter);
                    u64 num   = fma2(uni, uni, mul2(inter, earea));
                    u64 den   = mul2(uni, earea);

                    float n0, n1, d0, d1, a0, a1;
                    upk2(n0, n1, num);
                    upk2(d0, d1, den);
                    upk2(a0, a1, acc);
                    res[2 * q + 0][t] = fmaf(-2.0f, __fdividef(n0, d0), a0);
                    res[2 * q + 1][t] = fmaf(-2.0f, __fdividef(n1, d1), a1);
                }
            }

            o0[g] = make_float4(res[0][0], res[0][1], res[0][2], res[0][3]);
            o1[g] = make_float4(res[1][0], res[1][1], res[1][2], res[1][3]);
            o2[g] = make_float4(res[2][0], res[2][1], res[2][2], res[2][3]);
            o3[g] = make_float4(res[3][0], res[3][1], res[3][2], res[3][3]);
        }
    }
}

extern "C" void kernel_launch(void* const* d_in, const int* in_sizes, int n_in,
                              void* d_out, int out_size)
{
    const float* pred_logits = (const float*)d_in[0];
    const float* pred_boxes  = (const float*)d_in[1];
    const int*   tgt_labels  = (const int*)  d_in[2];
    const float* tgt_boxes   = (const float*)d_in[3];
    float* out = (float*)d_out;

    prep_kernel<<<(TT + 255) / 256, 256>>>(tgt_boxes);

    cudaFuncSetAttribute(matcher_kernel,
                         cudaFuncAttributeMaxDynamicSharedMemorySize, SMEM_BYTES);
    const int blocks = NROWS / ROWS_PER_BLOCK;   // 1800
    matcher_kernel<<<blocks, THREADS, SMEM_BYTES>>>(
        pred_logits, pred_boxes, tgt_labels, out);
}

// round 10
// speedup vs baseline: 1.0771x; 1.0481x over previous
#include <cuda_runtime.h>
#include <cuda_bf16.h>
#include <cstdint>

// Problem constants (fixed by setup_inputs)
#define BS    16
#define NQ    900
#define NC    151
#define NT    100
#define TT    (BS * NT)      // 1600 total targets
#define NROWS (BS * NQ)      // 14400 query rows
#define NG    (TT / 4)       // 400 target records

#define THREADS 256
#define ROWS_PER_BLOCK 8
#define PT_PITCH4 3          // prob table: 3 float4 slots per class

// ---- shared layout (static offsets, bytes) ----
// 80-byte records: 4 targets (cx,cy,w/2,h/2) + 4 areas
#define SM_REC   0                       // 400 * 80 = 32000
#define SM_PB    32000                   // float4[8]     128
#define SM_PT    32128                   // float[151*12] 7296 (padded)
#define SM_ID    39424                   // int[1600]    6400
#define SMEM_BYTES 45824

// cost = 5*L1(cxcywh) + (2 - p) - 2*(inter*earea + uni^2)/(uni*earea)
__device__ __forceinline__ float cost_elem(
    float tcx, float tcy, float twx, float twy, float tarea,
    float base,
    float pcx, float pcy, float pwx, float pwy, float parea)
{
    float adcx = fabsf(pcx - tcx), adcy = fabsf(pcy - tcy);
    float adwx = fabsf(pwx - twx), adwy = fabsf(pwy - twy);
    float sx   = pwx + twx,        sy   = pwy + twy;

    float acc = fmaf(5.0f,  adcx, base);
    acc = fmaf(5.0f,  adcy, acc);
    acc = fmaf(10.0f, adwx, acc);
    acc = fmaf(10.0f, adwy, acc);

    float mx = fmaxf(adcx, adwx), my = fmaxf(adcy, adwy);
    float iw = fmaxf(sx - mx, 0.0f), ih = fmaxf(sy - my, 0.0f);
    float ew = sx + mx,              eh = sy + my;

    float inter = iw * ih;
    float earea = ew * eh;
    float uni   = (parea + tarea) - inter;

    float num = fmaf(uni, uni, inter * earea);
    float q   = __fdividef(num, uni * earea);
    return fmaf(-2.0f, q, acc);
}

extern __shared__ __align__(16) char smem_raw[];

__global__ __launch_bounds__(THREADS, 3)
void matcher_kernel(const float* __restrict__ pred_logits,   // [NROWS, NC]
                    const float* __restrict__ pred_boxes,    // [NROWS, 4]
                    const int*   __restrict__ tgt_labels,    // [TT]
                    const float* __restrict__ tgt_boxes,     // [TT, 4]
                    float*       __restrict__ out)           // [NROWS, TT]
{
    float*  s_rec = reinterpret_cast<float*>(smem_raw + SM_REC);
    float4* s_pb  = reinterpret_cast<float4*>(smem_raw + SM_PB);
    float*  s_pT  = reinterpret_cast<float*>(smem_raw + SM_PT);
    int4*   s_id4 = reinterpret_cast<int4*>(smem_raw + SM_ID);

    const int tid  = threadIdx.x;
    const int lane = tid & 31;
    const int warp = tid >> 5;
    const int row_base = blockIdx.x * ROWS_PER_BLOCK;

    // ---- coalesced register-staged loads of raw targets + ids ----
    const float4* tb4 = reinterpret_cast<const float4*>(tgt_boxes);
    float4 raw[7];
    #pragma unroll
    for (int k = 0; k < 6; k++) raw[k] = tb4[tid + 256 * k];
    if (tid < TT - 1536) raw[6] = tb4[tid + 1536];

    const int4* id4g = reinterpret_cast<const int4*>(tgt_labels);
    int4 idr0 = id4g[tid < NG ? tid : 0];
    int4 idr1 = (tid < NG - 256) ? id4g[tid + 256] : make_int4(0, 0, 0, 0);

    if (tid < ROWS_PER_BLOCK)
        s_pb[tid] = reinterpret_cast<const float4*>(pred_boxes)[row_base + tid];

    // ---- warp-per-row softmax; store (2 - p) transposed, pitch 12 floats ----
    {
        const float* lg = pred_logits + (row_base + warp) * NC;
        float e[5];
        float s = 0.0f;
        #pragma unroll
        for (int k = 0; k < 5; k++) {
            int c = lane + 32 * k;
            e[k] = (c < NC) ? __expf(lg[c]) : 0.0f;
            s += e[k];
        }
        #pragma unroll
        for (int o = 16; o; o >>= 1)
            s += __shfl_xor_sync(0xffffffffu, s, o);
        const float inv = __fdividef(1.0f, s);
        const int grp = warp >> 2, r = warp & 3;
        #pragma unroll
        for (int k = 0; k < 5; k++) {
            int c = lane + 32 * k;
            if (c < NC) s_pT[(c * PT_PITCH4 + grp) * 4 + r] = fmaf(-e[k], inv, 2.0f);
        }
    }

    // ---- in-register transform -> 80B Rec layout in smem ----
    // raw i -> rec q = i/4, slot s = i%4: box at 20q + 4s, area at 20q + 16 + s
    #pragma unroll
    for (int k = 0; k < 6; k++) {
        int i = tid + 256 * k;
        int base = 20 * (i >> 2) + 4 * (i & 3);
        float4 t = raw[k];
        *reinterpret_cast<float4*>(s_rec + base) =
            make_float4(t.x, t.y, 0.5f * t.z, 0.5f * t.w);
        s_rec[20 * (i >> 2) + 16 + (i & 3)] = t.z * t.w;
    }
    if (tid < TT - 1536) {
        int i = tid + 1536;
        float4 t = raw[6];
        *reinterpret_cast<float4*>(s_rec + 20 * (i >> 2) + 4 * (i & 3)) =
            make_float4(t.x, t.y, 0.5f * t.z, 0.5f * t.w);
        s_rec[20 * (i >> 2) + 16 + (i & 3)] = t.z * t.w;
    }
    if (tid < NG) s_id4[tid] = idr0;
    if (tid < NG - 256) s_id4[tid + 256] = idr1;

    __syncthreads();   // probs + recs + ids all visible

    const float4* rec4 = reinterpret_cast<const float4*>(s_rec);
    const float4* probT4 = reinterpret_cast<const float4*>(s_pT);

    // ---- output: 2 groups of 4 rows; 4 targets x 4 rows per iteration ----
    #pragma unroll 1
    for (int grp = 0; grp < 2; grp++) {
        const int r0 = row_base + 4 * grp;

        float pcx[4], pcy[4], pwx[4], pwy[4], pa[4];
        #pragma unroll
        for (int r = 0; r < 4; r++) {
            float4 pb = s_pb[4 * grp + r];
            pcx[r] = pb.x;  pcy[r] = pb.y;
            pwx[r] = 0.5f * pb.z; pwy[r] = 0.5f * pb.w;
            pa[r]  = pb.z * pb.w;
        }

        float4* o0 = reinterpret_cast<float4*>(out + (size_t)(r0 + 0) * TT);
        float4* o1 = reinterpret_cast<float4*>(out + (size_t)(r0 + 1) * TT);
        float4* o2 = reinterpret_cast<float4*>(out + (size_t)(r0 + 2) * TT);
        float4* o3 = reinterpret_cast<float4*>(out + (size_t)(r0 + 3) * TT);

        #pragma unroll 1
        for (int g = tid; g < NG; g += THREADS) {
            float4 T0 = rec4[g * 5 + 0];
            float4 T1 = rec4[g * 5 + 1];
            float4 T2 = rec4[g * 5 + 2];
            float4 T3 = rec4[g * 5 + 3];
            float4 ta = rec4[g * 5 + 4];
            int4 ids = s_id4[g];

            float4 P0 = probT4[ids.x * PT_PITCH4 + grp];
            float4 P1 = probT4[ids.y * PT_PITCH4 + grp];
            float4 P2 = probT4[ids.z * PT_PITCH4 + grp];
            float4 P3 = probT4[ids.w * PT_PITCH4 + grp];
            const float* p0 = reinterpret_cast<const float*>(&P0);
            const float* p1 = reinterpret_cast<const float*>(&P1);
            const float* p2 = reinterpret_cast<const float*>(&P2);
            const float* p3 = reinterpret_cast<const float*>(&P3);

            float4 v0, v1, v2, v3;
            #pragma unroll
            for (int r = 0; r < 4; r++) {
                float4 v;
                v.x = cost_elem(T0.x, T0.y, T0.z, T0.w, ta.x, p0[r],
                                pcx[r], pcy[r], pwx[r], pwy[r], pa[r]);
                v.y = cost_elem(T1.x, T1.y, T1.z, T1.w, ta.y, p1[r],
                                pcx[r], pcy[r], pwx[r], pwy[r], pa[r]);
                v.z = cost_elem(T2.x, T2.y, T2.z, T2.w, ta.z, p2[r],
                                pcx[r], pcy[r], pwx[r], pwy[r], pa[r]);
                v.w = cost_elem(T3.x, T3.y, T3.z, T3.w, ta.w, p3[r],
                                pcx[r], pcy[r], pwx[r], pwy[r], pa[r]);
                if (r == 0) v0 = v; else if (r == 1) v1 = v;
                else if (r == 2) v2 = v; else v3 = v;
            }
            o0[g] = v0;
            o1[g] = v1;
            o2[g] = v2;
            o3[g] = v3;
        }
    }
}

extern "C" void kernel_launch(void* const* d_in, const int* in_sizes, int n_in,
                              void* d_out, int out_size)
{
    const float* pred_logits = (const float*)d_in[0];
    const float* pred_boxes  = (const float*)d_in[1];
    const int*   tgt_labels  = (const int*)  d_in[2];
    const float* tgt_boxes   = (const float*)d_in[3];
    float* out = (float*)d_out;

    cudaFuncSetAttribute(matcher_kernel,
                         cudaFuncAttributeMaxDynamicSharedMemorySize, SMEM_BYTES);
    const int blocks = NROWS / ROWS_PER_BLOCK;   // 1800
    matcher_kernel<<<blocks, THREADS, SMEM_BYTES>>>(
        pred_logits, pred_boxes, tgt_labels, tgt_boxes, out);
}